// round 7
// baseline (speedup 1.0000x reference)
#include <cuda_runtime.h>
#include <math.h>
#include <stdint.h>

// Problem constants
#define SV 512      // source length == target length
#define EV 512      // embed dim
#define HV 1024     // hidden dim
#define G4 4096     // 4*H
#define VV 32000    // vocab
#define NVT 250     // number of 128-wide V tiles (32000/128)

// ---------------- scratch (static device globals; no allocation) ----------
__device__ float    g_Xe[SV * G4];      // enc: x@Wih^T + bih + bhh  [512,4096]
__device__ float    g_Xd[SV * G4];      // dec: same
__device__ float    g_hbuf[2 * HV];     // double-buffered h
__device__ float    g_c0[HV];           // decoder initial c = tanh(enc_h)
__device__ float    g_hs[SV * HV];      // decoder hidden states [512,1024]
__device__ float    g_redm[SV * NVT];   // per-(t, vtile) local max
__device__ float    g_reds[SV * NVT];   // per-(t, vtile) local sumexp
__device__ unsigned g_flags[128];       // per-block epoch flags (barrier)

// ---------------- f32x2 packed FMA helpers (Blackwell FFMA2) --------------
__device__ __forceinline__ unsigned long long dup_f32(float x) {
    unsigned long long r;
    asm("mov.b64 %0, {%1, %1};" : "=l"(r) : "f"(x));
    return r;
}
__device__ __forceinline__ void fma_f32x2(unsigned long long& d,
                                          unsigned long long a,
                                          unsigned long long b) {
    asm("fma.rn.f32x2 %0, %1, %2, %0;" : "+l"(d) : "l"(a), "l"(b));
}
__device__ __forceinline__ float2 unpack2(unsigned long long v) {
    float2 r;
    asm("mov.b64 {%0, %1}, %2;" : "=f"(r.x), "=f"(r.y) : "l"(v));
    return r;
}

// ---------------------------------------------------------------------------
// Generic tiled C = A @ B^T (+bias) kernel. BM=BN=128, BK=32, 256 threads,
// 8x8 outputs/thread via packed f32x2 FMA.
//   GATHER: A row m is table[idx[m]] (embedding lookup)
//   EPI=0 : store C tile (+bias1+bias2) to C[m*N + n]
//   EPI=1 : per-row (max, sumexp) over this 128-col tile -> redm/reds
// ---------------------------------------------------------------------------
template <bool GATHER, int EPI>
__global__ void __launch_bounds__(256, 2)
gemm_kernel(const float* __restrict__ A, const int* __restrict__ idx,
            const float* __restrict__ B, const float* __restrict__ bias1,
            const float* __restrict__ bias2, float* __restrict__ C,
            float* __restrict__ redm, float* __restrict__ reds,
            int N, int K, int nvt) {
    __shared__ __align__(16) float As[32][132];
    __shared__ __align__(16) float Bs[32][132];
    __shared__ int idx_s[128];

    const int tid = threadIdx.x;
    const int tx = tid & 15;          // n-group 0..15
    const int ty = tid >> 4;          // m-group 0..15
    const int mbase = blockIdx.y * 128;
    const int nbase = blockIdx.x * 128;

    if (GATHER) {
        if (tid < 128) idx_s[tid] = idx[mbase + tid];
        __syncthreads();
    }

    unsigned long long acc[8][4];
#pragma unroll
    for (int i = 0; i < 8; i++)
#pragma unroll
        for (int j = 0; j < 4; j++) acc[i][j] = 0ull;

    for (int kc = 0; kc < K; kc += 32) {
        // load A tile -> As[k][m]
#pragma unroll
        for (int l = 0; l < 4; l++) {
            int f = tid + l * 256;            // 0..1023 (float4 units)
            int row = f >> 3;                 // 0..127
            int c4 = f & 7;                   // 0..7
            const float* ar = GATHER ? (A + (size_t)idx_s[row] * K)
                                     : (A + (size_t)(mbase + row) * K);
            float4 v = *(const float4*)(ar + kc + c4 * 4);
            As[c4 * 4 + 0][row] = v.x;
            As[c4 * 4 + 1][row] = v.y;
            As[c4 * 4 + 2][row] = v.z;
            As[c4 * 4 + 3][row] = v.w;
        }
        // load B tile -> Bs[k][n]
#pragma unroll
        for (int l = 0; l < 4; l++) {
            int f = tid + l * 256;
            int row = f >> 3;
            int c4 = f & 7;
            const float* br = B + (size_t)(nbase + row) * K;
            float4 v = *(const float4*)(br + kc + c4 * 4);
            Bs[c4 * 4 + 0][row] = v.x;
            Bs[c4 * 4 + 1][row] = v.y;
            Bs[c4 * 4 + 2][row] = v.z;
            Bs[c4 * 4 + 3][row] = v.w;
        }
        __syncthreads();

#pragma unroll
        for (int k = 0; k < 32; k++) {
            float4 a0 = *(const float4*)&As[k][ty * 8];
            float4 a1 = *(const float4*)&As[k][ty * 8 + 4];
            ulonglong2 bA = *(const ulonglong2*)&Bs[k][tx * 8];
            ulonglong2 bB = *(const ulonglong2*)&Bs[k][tx * 8 + 4];
            float av[8] = {a0.x, a0.y, a0.z, a0.w, a1.x, a1.y, a1.z, a1.w};
#pragma unroll
            for (int i = 0; i < 8; i++) {
                unsigned long long ad = dup_f32(av[i]);
                fma_f32x2(acc[i][0], ad, bA.x);
                fma_f32x2(acc[i][1], ad, bA.y);
                fma_f32x2(acc[i][2], ad, bB.x);
                fma_f32x2(acc[i][3], ad, bB.y);
            }
        }
        __syncthreads();
    }

    if (EPI == 0) {
#pragma unroll
        for (int i = 0; i < 8; i++) {
            int m = mbase + ty * 8 + i;
            float* cr = C + (size_t)m * N + nbase + tx * 8;
#pragma unroll
            for (int j = 0; j < 4; j++) {
                float2 v = unpack2(acc[i][j]);
                int n = nbase + tx * 8 + j * 2;
                float b0 = bias1[n], b1 = bias1[n + 1];
                if (bias2) { b0 += bias2[n]; b1 += bias2[n + 1]; }
                cr[j * 2 + 0] = v.x + b0;
                cr[j * 2 + 1] = v.y + b1;
            }
        }
    } else {
#pragma unroll
        for (int i = 0; i < 8; i++) {
            float vals[8];
#pragma unroll
            for (int j = 0; j < 4; j++) {
                float2 v = unpack2(acc[i][j]);
                int n = nbase + tx * 8 + j * 2;
                vals[j * 2 + 0] = v.x + bias1[n];
                vals[j * 2 + 1] = v.y + bias1[n + 1];
            }
            float mloc = vals[0];
#pragma unroll
            for (int j = 1; j < 8; j++) mloc = fmaxf(mloc, vals[j]);
#pragma unroll
            for (int o = 8; o; o >>= 1)
                mloc = fmaxf(mloc, __shfl_xor_sync(0xffffffffu, mloc, o));
            float sloc = 0.f;
#pragma unroll
            for (int j = 0; j < 8; j++) sloc += __expf(vals[j] - mloc);
#pragma unroll
            for (int o = 8; o; o >>= 1)
                sloc += __shfl_xor_sync(0xffffffffu, sloc, o);
            if (tx == 0) {
                int m = mbase + ty * 8 + i;
                redm[(size_t)m * nvt + blockIdx.x] = mloc;
                reds[(size_t)m * nvt + blockIdx.x] = sloc;
            }
        }
    }
}

// ---------------------------------------------------------------------------
// Persistent LSTM kernel: 128 blocks x 256 threads. Block b owns 8 hidden
// channels (ch0 = 8b) => 32 rows of Whh, kept in SMEM (128 KB).
// Barrier: per-block epoch flags. Each block release-stores its flag = t+1
// (parallel arrivals, no single-address atomic serialization); 128 threads
// each tight-poll one flag with acquire loads (NO nanosleep — its wakeup
// quantum sat on the serial chain and cost ~1.1 us/step in R6).
// ---------------------------------------------------------------------------
__global__ void __launch_bounds__(256, 1)
lstm_kernel(const float* __restrict__ Whh, const float* __restrict__ X,
            const float* __restrict__ cinit, float* __restrict__ cout_,
            float* __restrict__ hs_out, int steps) {
    extern __shared__ __align__(16) float Ws[];   // 32*1024 floats
    __shared__ __align__(16) float hs_s[HV];
    __shared__ float gates_s[32];

    const int tid = threadIdx.x;
    const int ch0 = blockIdx.x * 8;

    // load this block's 32 Whh rows into SMEM (coalesced float4)
#pragma unroll
    for (int l = 0; l < 32; l++) {
        int f = tid + l * 256;        // float4 index 0..8191
        int r = f >> 8;               // row 0..31
        int c4 = f & 255;             // 0..255
        int gate = r >> 3, lc = r & 7;
        float4 v = *(const float4*)(Whh + (size_t)(gate * HV + ch0 + lc) * HV + c4 * 4);
        *(float4*)&Ws[r * HV + c4 * 4] = v;
    }
    float c_val = 0.f;
    if (tid < 8) c_val = cinit ? cinit[ch0 + tid] : 0.f;
    __syncthreads();

    const int warp = tid >> 5;
    const int lane = tid & 31;
    const int r0 = warp * 4;          // 4 rows per warp

    for (int t = 0; t < steps; t++) {
        // Prefetch this step's X gate pre-activations (independent of h) so
        // the LDG latency overlaps the GEMV instead of the activation path.
        float xi, xf, xg, xo;
        if (tid < 8) {
            const float* Xr = X + (size_t)t * G4 + ch0 + tid;
            xi = Xr[0 * HV];
            xf = Xr[1 * HV];
            xg = Xr[2 * HV];
            xo = Xr[3 * HV];
        }

        // load h(t) from global (L2-coherent path; L1 may be stale)
        float4 hv = __ldcg(((const float4*)(g_hbuf + (t & 1) * HV)) + tid);
        *(float4*)&hs_s[tid * 4] = hv;
        __syncthreads();

        float4 s0 = make_float4(0.f, 0.f, 0.f, 0.f);
        float4 s1 = s0, s2 = s0, s3 = s0;
#pragma unroll
        for (int i = 0; i < 8; i++) {
            int k = lane * 4 + i * 128;
            float4 h4 = *(const float4*)&hs_s[k];
            float4 w0 = *(const float4*)&Ws[(r0 + 0) * HV + k];
            float4 w1 = *(const float4*)&Ws[(r0 + 1) * HV + k];
            float4 w2 = *(const float4*)&Ws[(r0 + 2) * HV + k];
            float4 w3 = *(const float4*)&Ws[(r0 + 3) * HV + k];
            s0.x = fmaf(w0.x, h4.x, s0.x); s0.y = fmaf(w0.y, h4.y, s0.y);
            s0.z = fmaf(w0.z, h4.z, s0.z); s0.w = fmaf(w0.w, h4.w, s0.w);
            s1.x = fmaf(w1.x, h4.x, s1.x); s1.y = fmaf(w1.y, h4.y, s1.y);
            s1.z = fmaf(w1.z, h4.z, s1.z); s1.w = fmaf(w1.w, h4.w, s1.w);
            s2.x = fmaf(w2.x, h4.x, s2.x); s2.y = fmaf(w2.y, h4.y, s2.y);
            s2.z = fmaf(w2.z, h4.z, s2.z); s2.w = fmaf(w2.w, h4.w, s2.w);
            s3.x = fmaf(w3.x, h4.x, s3.x); s3.y = fmaf(w3.y, h4.y, s3.y);
            s3.z = fmaf(w3.z, h4.z, s3.z); s3.w = fmaf(w3.w, h4.w, s3.w);
        }
        float v0 = s0.x + s0.y + s0.z + s0.w;
        float v1 = s1.x + s1.y + s1.z + s1.w;
        float v2 = s2.x + s2.y + s2.z + s2.w;
        float v3 = s3.x + s3.y + s3.z + s3.w;
#pragma unroll
        for (int o = 16; o; o >>= 1) {
            v0 += __shfl_xor_sync(0xffffffffu, v0, o);
            v1 += __shfl_xor_sync(0xffffffffu, v1, o);
            v2 += __shfl_xor_sync(0xffffffffu, v2, o);
            v3 += __shfl_xor_sync(0xffffffffu, v3, o);
        }
        if (lane == 0) {
            gates_s[r0 + 0] = v0;
            gates_s[r0 + 1] = v1;
            gates_s[r0 + 2] = v2;
            gates_s[r0 + 3] = v3;
        }
        __syncthreads();

        if (tid < 8) {
            int lc = tid;
            float gi = gates_s[0 * 8 + lc] + xi;
            float gf = gates_s[1 * 8 + lc] + xf;
            float gg = gates_s[2 * 8 + lc] + xg;
            float go = gates_s[3 * 8 + lc] + xo;
            float iv = 1.f / (1.f + expf(-gi));
            float fv = 1.f / (1.f + expf(-gf));
            float gv = tanhf(gg);
            float ov = 1.f / (1.f + expf(-go));
            c_val = fv * c_val + iv * gv;
            float hval = ov * tanhf(c_val);
            g_hbuf[((t + 1) & 1) * HV + ch0 + lc] = hval;
            if (hs_out) hs_out[(size_t)t * HV + ch0 + lc] = hval;
            if (cout_ && t == steps - 1) cout_[ch0 + lc] = tanhf(hval);
            __threadfence();   // make h(t+1) stores visible before flag store
        }
        __syncthreads();

        // ---- flag barrier: parallel arrivals, distributed tight polling ----
        if (tid == 0) {
            asm volatile("st.release.gpu.global.u32 [%0], %1;"
                         :: "l"(g_flags + blockIdx.x), "r"((unsigned)(t + 1))
                         : "memory");
        }
        if (tid < 128) {
            unsigned v;
            do {
                asm volatile("ld.acquire.gpu.global.u32 %0, [%1];"
                             : "=r"(v) : "l"(g_flags + tid) : "memory");
            } while (v < (unsigned)(t + 1));
        }
        __syncthreads();
    }
}

// ---------------------------------------------------------------------------
// Finalize: one warp per target position t.
//   loss[t] = logsumexp_v(logits[t]) - logit[t, target[t]]
// ---------------------------------------------------------------------------
__global__ void finalize_kernel(const int* __restrict__ target,
                                const float* __restrict__ Wout,
                                const float* __restrict__ bout,
                                const float* __restrict__ hs,
                                const float* __restrict__ redm,
                                const float* __restrict__ reds,
                                float* __restrict__ out) {
    int gwarp = (blockIdx.x * blockDim.x + threadIdx.x) >> 5;
    int lane = threadIdx.x & 31;
    if (gwarp >= SV) return;
    int t = gwarp;

    float M = -INFINITY, S = 0.f;
    for (int c = lane; c < NVT; c += 32) {
        float m = redm[(size_t)t * NVT + c];
        float s = reds[(size_t)t * NVT + c];
        float nm = fmaxf(M, m);
        S = S * __expf(M - nm) + s * __expf(m - nm);
        M = nm;
    }
#pragma unroll
    for (int o = 16; o; o >>= 1) {
        float m2 = __shfl_xor_sync(0xffffffffu, M, o);
        float s2 = __shfl_xor_sync(0xffffffffu, S, o);
        float nm = fmaxf(M, m2);
        S = S * __expf(M - nm) + s2 * __expf(m2 - nm);
        M = nm;
    }

    int tg = target[t];
    float dot = 0.f;
    const float* hr = hs + (size_t)t * HV;
    const float* wr = Wout + (size_t)tg * HV;
#pragma unroll
    for (int k = lane * 4; k < HV; k += 128) {
        float4 h4 = *(const float4*)(hr + k);
        float4 w4 = *(const float4*)(wr + k);
        dot += h4.x * w4.x + h4.y * w4.y + h4.z * w4.z + h4.w * w4.w;
    }
#pragma unroll
    for (int o = 16; o; o >>= 1) dot += __shfl_xor_sync(0xffffffffu, dot, o);

    if (lane == 0) out[t] = (M + logf(S)) - (dot + bout[tg]);
}

// ---------------------------------------------------------------------------
extern "C" void kernel_launch(void* const* d_in, const int* in_sizes, int n_in,
                              void* d_out, int out_size) {
    (void)in_sizes; (void)n_in; (void)out_size;
    const int*   src  = (const int*)d_in[0];
    const int*   tgt  = (const int*)d_in[1];
    const float* eEmb = (const float*)d_in[2];
    const float* eWih = (const float*)d_in[3];
    const float* eWhh = (const float*)d_in[4];
    const float* eBih = (const float*)d_in[5];
    const float* eBhh = (const float*)d_in[6];
    const float* dEmb = (const float*)d_in[7];
    const float* dWih = (const float*)d_in[8];
    const float* dWhh = (const float*)d_in[9];
    const float* dBih = (const float*)d_in[10];
    const float* dBhh = (const float*)d_in[11];
    const float* Wout = (const float*)d_in[12];
    const float* bout = (const float*)d_in[13];
    float* out = (float*)d_out;

    float *Xe, *Xd, *hbuf, *c0, *hs, *redm, *reds;
    unsigned* flags;
    cudaGetSymbolAddress((void**)&Xe, g_Xe);
    cudaGetSymbolAddress((void**)&Xd, g_Xd);
    cudaGetSymbolAddress((void**)&hbuf, g_hbuf);
    cudaGetSymbolAddress((void**)&c0, g_c0);
    cudaGetSymbolAddress((void**)&hs, g_hs);
    cudaGetSymbolAddress((void**)&redm, g_redm);
    cudaGetSymbolAddress((void**)&reds, g_reds);
    cudaGetSymbolAddress((void**)&flags, g_flags);

    const int lstm_smem = 32 * HV * (int)sizeof(float);   // 128 KB
    cudaFuncSetAttribute(lstm_kernel,
                         cudaFuncAttributeMaxDynamicSharedMemorySize, lstm_smem);

    cudaMemsetAsync(hbuf, 0, 2 * HV * sizeof(float));
    cudaMemsetAsync(flags, 0, 128 * sizeof(unsigned));

    // Precompute X = embed(tok) @ Wih^T + bih + bhh for both phases
    dim3 gX(G4 / 128, SV / 128);   // 32 x 4
    gemm_kernel<true, 0><<<gX, 256>>>(eEmb, src, eWih, eBih, eBhh,
                                      Xe, nullptr, nullptr, G4, EV, 0);
    gemm_kernel<true, 0><<<gX, 256>>>(dEmb, tgt, dWih, dBih, dBhh,
                                      Xd, nullptr, nullptr, G4, EV, 0);

    // Encoder recurrence (h0=c0=0). Final h lands in hbuf[0]; c0 = tanh(h).
    lstm_kernel<<<128, 256, lstm_smem>>>(eWhh, Xe, nullptr, c0, nullptr, SV);
    cudaMemsetAsync(flags, 0, 128 * sizeof(unsigned));
    // Decoder recurrence, teacher-forced; stores all h_t.
    lstm_kernel<<<128, 256, lstm_smem>>>(dWhh, Xd, c0, nullptr, hs, SV);

    // Output logits GEMM + per-tile streaming logsumexp stats
    dim3 gO(NVT, SV / 128);        // 250 x 4
    gemm_kernel<false, 1><<<gO, 256>>>(hs, nullptr, Wout, bout, nullptr,
                                       nullptr, redm, reds, VV, HV, NVT);

    // Combine tile stats + target logit -> losses
    finalize_kernel<<<(SV * 32 + 255) / 256, 256>>>(tgt, Wout, bout, hs,
                                                    redm, reds, out);
}

// round 8
// speedup vs baseline: 1.8503x; 1.8503x over previous
#include <cuda_runtime.h>
#include <math.h>
#include <stdint.h>

// Problem constants
#define SV 512      // source length == target length
#define EV 512      // embed dim
#define HV 1024     // hidden dim
#define G4 4096     // 4*H
#define VV 32000    // vocab
#define NVT 250     // number of 128-wide V tiles (32000/128)

// ---------------- scratch (static device globals; no allocation) ----------
__device__ float    g_Xe[SV * G4];      // enc: x@Wih^T + bih + bhh  [512,4096]
__device__ float    g_Xd[SV * G4];      // dec: same
__device__ float    g_hbuf[2 * HV];     // double-buffered h
__device__ float    g_c0[HV];           // decoder initial c = tanh(enc_h)
__device__ float    g_hs[SV * HV];      // decoder hidden states [512,1024]
__device__ float    g_redm[SV * NVT];   // per-(t, vtile) local max
__device__ float    g_reds[SV * NVT];   // per-(t, vtile) local sumexp
__device__ unsigned g_bar;              // single barrier counter

// ---------------- f32x2 packed FMA helpers (Blackwell FFMA2) --------------
__device__ __forceinline__ unsigned long long dup_f32(float x) {
    unsigned long long r;
    asm("mov.b64 %0, {%1, %1};" : "=l"(r) : "f"(x));
    return r;
}
__device__ __forceinline__ void fma_f32x2(unsigned long long& d,
                                          unsigned long long a,
                                          unsigned long long b) {
    asm("fma.rn.f32x2 %0, %1, %2, %0;" : "+l"(d) : "l"(a), "l"(b));
}
__device__ __forceinline__ float2 unpack2(unsigned long long v) {
    float2 r;
    asm("mov.b64 {%0, %1}, %2;" : "=f"(r.x), "=f"(r.y) : "l"(v));
    return r;
}

// ---------------------------------------------------------------------------
// Generic tiled C = A @ B^T (+bias) kernel. BM=BN=128, BK=32, 256 threads,
// 8x8 outputs/thread via packed f32x2 FMA.
//   GATHER: A row m is table[idx[m]] (embedding lookup)
//   EPI=0 : store C tile (+bias1+bias2) to C[m*N + n]
//   EPI=1 : per-row (max, sumexp) over this 128-col tile -> redm/reds
// ---------------------------------------------------------------------------
template <bool GATHER, int EPI>
__global__ void __launch_bounds__(256, 2)
gemm_kernel(const float* __restrict__ A, const int* __restrict__ idx,
            const float* __restrict__ B, const float* __restrict__ bias1,
            const float* __restrict__ bias2, float* __restrict__ C,
            float* __restrict__ redm, float* __restrict__ reds,
            int N, int K, int nvt) {
    __shared__ __align__(16) float As[32][132];
    __shared__ __align__(16) float Bs[32][132];
    __shared__ int idx_s[128];

    const int tid = threadIdx.x;
    const int tx = tid & 15;          // n-group 0..15
    const int ty = tid >> 4;          // m-group 0..15
    const int mbase = blockIdx.y * 128;
    const int nbase = blockIdx.x * 128;

    if (GATHER) {
        if (tid < 128) idx_s[tid] = idx[mbase + tid];
        __syncthreads();
    }

    unsigned long long acc[8][4];
#pragma unroll
    for (int i = 0; i < 8; i++)
#pragma unroll
        for (int j = 0; j < 4; j++) acc[i][j] = 0ull;

    for (int kc = 0; kc < K; kc += 32) {
        // load A tile -> As[k][m]
#pragma unroll
        for (int l = 0; l < 4; l++) {
            int f = tid + l * 256;            // 0..1023 (float4 units)
            int row = f >> 3;                 // 0..127
            int c4 = f & 7;                   // 0..7
            const float* ar = GATHER ? (A + (size_t)idx_s[row] * K)
                                     : (A + (size_t)(mbase + row) * K);
            float4 v = *(const float4*)(ar + kc + c4 * 4);
            As[c4 * 4 + 0][row] = v.x;
            As[c4 * 4 + 1][row] = v.y;
            As[c4 * 4 + 2][row] = v.z;
            As[c4 * 4 + 3][row] = v.w;
        }
        // load B tile -> Bs[k][n]
#pragma unroll
        for (int l = 0; l < 4; l++) {
            int f = tid + l * 256;
            int row = f >> 3;
            int c4 = f & 7;
            const float* br = B + (size_t)(nbase + row) * K;
            float4 v = *(const float4*)(br + kc + c4 * 4);
            Bs[c4 * 4 + 0][row] = v.x;
            Bs[c4 * 4 + 1][row] = v.y;
            Bs[c4 * 4 + 2][row] = v.z;
            Bs[c4 * 4 + 3][row] = v.w;
        }
        __syncthreads();

#pragma unroll
        for (int k = 0; k < 32; k++) {
            float4 a0 = *(const float4*)&As[k][ty * 8];
            float4 a1 = *(const float4*)&As[k][ty * 8 + 4];
            ulonglong2 bA = *(const ulonglong2*)&Bs[k][tx * 8];
            ulonglong2 bB = *(const ulonglong2*)&Bs[k][tx * 8 + 4];
            float av[8] = {a0.x, a0.y, a0.z, a0.w, a1.x, a1.y, a1.z, a1.w};
#pragma unroll
            for (int i = 0; i < 8; i++) {
                unsigned long long ad = dup_f32(av[i]);
                fma_f32x2(acc[i][0], ad, bA.x);
                fma_f32x2(acc[i][1], ad, bA.y);
                fma_f32x2(acc[i][2], ad, bB.x);
                fma_f32x2(acc[i][3], ad, bB.y);
            }
        }
        __syncthreads();
    }

    if (EPI == 0) {
#pragma unroll
        for (int i = 0; i < 8; i++) {
            int m = mbase + ty * 8 + i;
            float* cr = C + (size_t)m * N + nbase + tx * 8;
#pragma unroll
            for (int j = 0; j < 4; j++) {
                float2 v = unpack2(acc[i][j]);
                int n = nbase + tx * 8 + j * 2;
                float b0 = bias1[n], b1 = bias1[n + 1];
                if (bias2) { b0 += bias2[n]; b1 += bias2[n + 1]; }
                cr[j * 2 + 0] = v.x + b0;
                cr[j * 2 + 1] = v.y + b1;
            }
        }
    } else {
#pragma unroll
        for (int i = 0; i < 8; i++) {
            float vals[8];
#pragma unroll
            for (int j = 0; j < 4; j++) {
                float2 v = unpack2(acc[i][j]);
                int n = nbase + tx * 8 + j * 2;
                vals[j * 2 + 0] = v.x + bias1[n];
                vals[j * 2 + 1] = v.y + bias1[n + 1];
            }
            float mloc = vals[0];
#pragma unroll
            for (int j = 1; j < 8; j++) mloc = fmaxf(mloc, vals[j]);
#pragma unroll
            for (int o = 8; o; o >>= 1)
                mloc = fmaxf(mloc, __shfl_xor_sync(0xffffffffu, mloc, o));
            float sloc = 0.f;
#pragma unroll
            for (int j = 0; j < 8; j++) sloc += __expf(vals[j] - mloc);
#pragma unroll
            for (int o = 8; o; o >>= 1)
                sloc += __shfl_xor_sync(0xffffffffu, sloc, o);
            if (tx == 0) {
                int m = mbase + ty * 8 + i;
                redm[(size_t)m * nvt + blockIdx.x] = mloc;
                reds[(size_t)m * nvt + blockIdx.x] = sloc;
            }
        }
    }
}

// ---------------------------------------------------------------------------
// Persistent LSTM kernel: 128 blocks x 256 threads. Block b owns 8 hidden
// channels (ch0 = 8b) => 32 rows of Whh, kept in SMEM (128 KB).
// Barrier (lesson from R6/R7: exactly ONE poller per block, ONE counter):
//   arrivals  : tid0 red.release.gpu.add (pipelined ~0.85cyc/op at LTS; the
//               release + consumer acquire replaces per-producer MEMBAR.GPU)
//   wait      : tid0 tight acquire-poll on the counter (128 pollers total)
// ---------------------------------------------------------------------------
__global__ void __launch_bounds__(256, 1)
lstm_kernel(const float* __restrict__ Whh, const float* __restrict__ X,
            const float* __restrict__ cinit, float* __restrict__ cout_,
            float* __restrict__ hs_out, int steps) {
    extern __shared__ __align__(16) float Ws[];   // 32*1024 floats
    __shared__ __align__(16) float hs_s[HV];
    __shared__ float gates_s[32];

    const int tid = threadIdx.x;
    const int ch0 = blockIdx.x * 8;

    // load this block's 32 Whh rows into SMEM (coalesced float4)
#pragma unroll
    for (int l = 0; l < 32; l++) {
        int f = tid + l * 256;        // float4 index 0..8191
        int r = f >> 8;               // row 0..31
        int c4 = f & 255;             // 0..255
        int gate = r >> 3, lc = r & 7;
        float4 v = *(const float4*)(Whh + (size_t)(gate * HV + ch0 + lc) * HV + c4 * 4);
        *(float4*)&Ws[r * HV + c4 * 4] = v;
    }
    float c_val = 0.f;
    if (tid < 8) c_val = cinit ? cinit[ch0 + tid] : 0.f;
    __syncthreads();

    const int warp = tid >> 5;
    const int lane = tid & 31;
    const int r0 = warp * 4;          // 4 rows per warp

    unsigned* barp = &g_bar;

    for (int t = 0; t < steps; t++) {
        // Prefetch this step's X gate pre-activations (independent of h) so
        // the LDG latency overlaps the GEMV instead of the activation path.
        float xi, xf, xg, xo;
        if (tid < 8) {
            const float* Xr = X + (size_t)t * G4 + ch0 + tid;
            xi = Xr[0 * HV];
            xf = Xr[1 * HV];
            xg = Xr[2 * HV];
            xo = Xr[3 * HV];
        }

        // load h(t) from global (L2-coherent path; L1 may be stale)
        float4 hv = __ldcg(((const float4*)(g_hbuf + (t & 1) * HV)) + tid);
        *(float4*)&hs_s[tid * 4] = hv;
        __syncthreads();

        float4 s0 = make_float4(0.f, 0.f, 0.f, 0.f);
        float4 s1 = s0, s2 = s0, s3 = s0;
#pragma unroll
        for (int i = 0; i < 8; i++) {
            int k = lane * 4 + i * 128;
            float4 h4 = *(const float4*)&hs_s[k];
            float4 w0 = *(const float4*)&Ws[(r0 + 0) * HV + k];
            float4 w1 = *(const float4*)&Ws[(r0 + 1) * HV + k];
            float4 w2 = *(const float4*)&Ws[(r0 + 2) * HV + k];
            float4 w3 = *(const float4*)&Ws[(r0 + 3) * HV + k];
            s0.x = fmaf(w0.x, h4.x, s0.x); s0.y = fmaf(w0.y, h4.y, s0.y);
            s0.z = fmaf(w0.z, h4.z, s0.z); s0.w = fmaf(w0.w, h4.w, s0.w);
            s1.x = fmaf(w1.x, h4.x, s1.x); s1.y = fmaf(w1.y, h4.y, s1.y);
            s1.z = fmaf(w1.z, h4.z, s1.z); s1.w = fmaf(w1.w, h4.w, s1.w);
            s2.x = fmaf(w2.x, h4.x, s2.x); s2.y = fmaf(w2.y, h4.y, s2.y);
            s2.z = fmaf(w2.z, h4.z, s2.z); s2.w = fmaf(w2.w, h4.w, s2.w);
            s3.x = fmaf(w3.x, h4.x, s3.x); s3.y = fmaf(w3.y, h4.y, s3.y);
            s3.z = fmaf(w3.z, h4.z, s3.z); s3.w = fmaf(w3.w, h4.w, s3.w);
        }
        float v0 = s0.x + s0.y + s0.z + s0.w;
        float v1 = s1.x + s1.y + s1.z + s1.w;
        float v2 = s2.x + s2.y + s2.z + s2.w;
        float v3 = s3.x + s3.y + s3.z + s3.w;
#pragma unroll
        for (int o = 16; o; o >>= 1) {
            v0 += __shfl_xor_sync(0xffffffffu, v0, o);
            v1 += __shfl_xor_sync(0xffffffffu, v1, o);
            v2 += __shfl_xor_sync(0xffffffffu, v2, o);
            v3 += __shfl_xor_sync(0xffffffffu, v3, o);
        }
        if (lane == 0) {
            gates_s[r0 + 0] = v0;
            gates_s[r0 + 1] = v1;
            gates_s[r0 + 2] = v2;
            gates_s[r0 + 3] = v3;
        }
        __syncthreads();

        if (tid < 8) {
            int lc = tid;
            float gi = gates_s[0 * 8 + lc] + xi;
            float gf = gates_s[1 * 8 + lc] + xf;
            float gg = gates_s[2 * 8 + lc] + xg;
            float go = gates_s[3 * 8 + lc] + xo;
            float iv = 1.f / (1.f + expf(-gi));
            float fv = 1.f / (1.f + expf(-gf));
            float gv = tanhf(gg);
            float ov = 1.f / (1.f + expf(-go));
            c_val = fv * c_val + iv * gv;
            float hval = ov * tanhf(c_val);
            g_hbuf[((t + 1) & 1) * HV + ch0 + lc] = hval;
            if (hs_out) hs_out[(size_t)t * HV + ch0 + lc] = hval;
            if (cout_ && t == steps - 1) cout_[ch0 + lc] = tanhf(hval);
        }
        // Intra-block HB edge: producers' h stores happen-before tid0's
        // release-arrival below; consumers chain through their acquire poll.
        __syncthreads();

        if (tid == 0) {
            asm volatile("red.release.gpu.global.add.u32 [%0], 1;"
                         :: "l"(barp) : "memory");
            unsigned tgt = (unsigned)(t + 1) * gridDim.x;
            unsigned v;
            do {
                asm volatile("ld.acquire.gpu.global.u32 %0, [%1];"
                             : "=r"(v) : "l"(barp) : "memory");
            } while (v < tgt);
        }
        __syncthreads();
    }
}

// ---------------------------------------------------------------------------
// Finalize: one warp per target position t.
//   loss[t] = logsumexp_v(logits[t]) - logit[t, target[t]]
// ---------------------------------------------------------------------------
__global__ void finalize_kernel(const int* __restrict__ target,
                                const float* __restrict__ Wout,
                                const float* __restrict__ bout,
                                const float* __restrict__ hs,
                                const float* __restrict__ redm,
                                const float* __restrict__ reds,
                                float* __restrict__ out) {
    int gwarp = (blockIdx.x * blockDim.x + threadIdx.x) >> 5;
    int lane = threadIdx.x & 31;
    if (gwarp >= SV) return;
    int t = gwarp;

    float M = -INFINITY, S = 0.f;
    for (int c = lane; c < NVT; c += 32) {
        float m = redm[(size_t)t * NVT + c];
        float s = reds[(size_t)t * NVT + c];
        float nm = fmaxf(M, m);
        S = S * __expf(M - nm) + s * __expf(m - nm);
        M = nm;
    }
#pragma unroll
    for (int o = 16; o; o >>= 1) {
        float m2 = __shfl_xor_sync(0xffffffffu, M, o);
        float s2 = __shfl_xor_sync(0xffffffffu, S, o);
        float nm = fmaxf(M, m2);
        S = S * __expf(M - nm) + s2 * __expf(m2 - nm);
        M = nm;
    }

    int tg = target[t];
    float dot = 0.f;
    const float* hr = hs + (size_t)t * HV;
    const float* wr = Wout + (size_t)tg * HV;
#pragma unroll
    for (int k = lane * 4; k < HV; k += 128) {
        float4 h4 = *(const float4*)(hr + k);
        float4 w4 = *(const float4*)(wr + k);
        dot += h4.x * w4.x + h4.y * w4.y + h4.z * w4.z + h4.w * w4.w;
    }
#pragma unroll
    for (int o = 16; o; o >>= 1) dot += __shfl_xor_sync(0xffffffffu, dot, o);

    if (lane == 0) out[t] = (M + logf(S)) - (dot + bout[tg]);
}

// ---------------------------------------------------------------------------
extern "C" void kernel_launch(void* const* d_in, const int* in_sizes, int n_in,
                              void* d_out, int out_size) {
    (void)in_sizes; (void)n_in; (void)out_size;
    const int*   src  = (const int*)d_in[0];
    const int*   tgt  = (const int*)d_in[1];
    const float* eEmb = (const float*)d_in[2];
    const float* eWih = (const float*)d_in[3];
    const float* eWhh = (const float*)d_in[4];
    const float* eBih = (const float*)d_in[5];
    const float* eBhh = (const float*)d_in[6];
    const float* dEmb = (const float*)d_in[7];
    const float* dWih = (const float*)d_in[8];
    const float* dWhh = (const float*)d_in[9];
    const float* dBih = (const float*)d_in[10];
    const float* dBhh = (const float*)d_in[11];
    const float* Wout = (const float*)d_in[12];
    const float* bout = (const float*)d_in[13];
    float* out = (float*)d_out;

    float *Xe, *Xd, *hbuf, *c0, *hs, *redm, *reds;
    unsigned* bar;
    cudaGetSymbolAddress((void**)&Xe, g_Xe);
    cudaGetSymbolAddress((void**)&Xd, g_Xd);
    cudaGetSymbolAddress((void**)&hbuf, g_hbuf);
    cudaGetSymbolAddress((void**)&c0, g_c0);
    cudaGetSymbolAddress((void**)&hs, g_hs);
    cudaGetSymbolAddress((void**)&redm, g_redm);
    cudaGetSymbolAddress((void**)&reds, g_reds);
    cudaGetSymbolAddress((void**)&bar, g_bar);

    const int lstm_smem = 32 * HV * (int)sizeof(float);   // 128 KB
    cudaFuncSetAttribute(lstm_kernel,
                         cudaFuncAttributeMaxDynamicSharedMemorySize, lstm_smem);

    cudaMemsetAsync(hbuf, 0, 2 * HV * sizeof(float));
    cudaMemsetAsync(bar, 0, sizeof(unsigned));

    // Precompute X = embed(tok) @ Wih^T + bih + bhh for both phases
    dim3 gX(G4 / 128, SV / 128);   // 32 x 4
    gemm_kernel<true, 0><<<gX, 256>>>(eEmb, src, eWih, eBih, eBhh,
                                      Xe, nullptr, nullptr, G4, EV, 0);
    gemm_kernel<true, 0><<<gX, 256>>>(dEmb, tgt, dWih, dBih, dBhh,
                                      Xd, nullptr, nullptr, G4, EV, 0);

    // Encoder recurrence (h0=c0=0). Final h lands in hbuf[0]; c0 = tanh(h).
    lstm_kernel<<<128, 256, lstm_smem>>>(eWhh, Xe, nullptr, c0, nullptr, SV);
    cudaMemsetAsync(bar, 0, sizeof(unsigned));
    // Decoder recurrence, teacher-forced; stores all h_t.
    lstm_kernel<<<128, 256, lstm_smem>>>(dWhh, Xd, c0, nullptr, hs, SV);

    // Output logits GEMM + per-tile streaming logsumexp stats
    dim3 gO(NVT, SV / 128);        // 250 x 4
    gemm_kernel<false, 1><<<gO, 256>>>(hs, nullptr, Wout, bout, nullptr,
                                       nullptr, redm, reds, VV, HV, NVT);

    // Combine tile stats + target logit -> losses
    finalize_kernel<<<(SV * 32 + 255) / 256, 256>>>(tgt, Wout, bout, hs,
                                                    redm, reds, out);
}

// round 9
// speedup vs baseline: 2.1623x; 1.1686x over previous
#include <cuda_runtime.h>
#include <math.h>
#include <stdint.h>

// Problem constants
#define SV 512      // source length == target length
#define EV 512      // embed dim
#define HV 1024     // hidden dim
#define G4 4096     // 4*H
#define VV 32000    // vocab
#define NVT 250     // number of 128-wide V tiles (32000/128)

// ---------------- scratch (static device globals; no allocation) ----------
__device__ float    g_Xe[SV * G4];      // enc: x@Wih^T + bih + bhh  [512,4096]
__device__ float    g_Xd[SV * G4];      // dec: same
__device__ float    g_hbuf[2 * HV];     // double-buffered h
__device__ float    g_c0[HV];           // decoder initial c = tanh(enc_h)
__device__ float    g_hs[SV * HV];      // decoder hidden states [512,1024]
__device__ float    g_redm[SV * NVT];   // per-(t, vtile) local max
__device__ float    g_reds[SV * NVT];   // per-(t, vtile) local sumexp
__device__ unsigned g_bar;              // single barrier counter

// ---------------- f32x2 packed FMA helpers (Blackwell FFMA2) --------------
__device__ __forceinline__ unsigned long long dup_f32(float x) {
    unsigned long long r;
    asm("mov.b64 %0, {%1, %1};" : "=l"(r) : "f"(x));
    return r;
}
__device__ __forceinline__ void fma_f32x2(unsigned long long& d,
                                          unsigned long long a,
                                          unsigned long long b) {
    asm("fma.rn.f32x2 %0, %1, %2, %0;" : "+l"(d) : "l"(a), "l"(b));
}
__device__ __forceinline__ float2 unpack2(unsigned long long v) {
    float2 r;
    asm("mov.b64 {%0, %1}, %2;" : "=f"(r.x), "=f"(r.y) : "l"(v));
    return r;
}

// ---------------------------------------------------------------------------
// Generic tiled C = A @ B^T (+bias) kernel. BM=BN=128, BK=32, 256 threads,
// 8x8 outputs/thread via packed f32x2 FMA.
//   GATHER: A row m is table[idx[m]] (embedding lookup)
//   EPI=0 : store C tile (+bias1+bias2) to C[m*N + n]
//   EPI=1 : per-row (max, sumexp) over this 128-col tile -> redm/reds
// ---------------------------------------------------------------------------
template <bool GATHER, int EPI>
__global__ void __launch_bounds__(256, 2)
gemm_kernel(const float* __restrict__ A, const int* __restrict__ idx,
            const float* __restrict__ B, const float* __restrict__ bias1,
            const float* __restrict__ bias2, float* __restrict__ C,
            float* __restrict__ redm, float* __restrict__ reds,
            int N, int K, int nvt) {
    __shared__ __align__(16) float As[32][132];
    __shared__ __align__(16) float Bs[32][132];
    __shared__ int idx_s[128];

    const int tid = threadIdx.x;
    const int tx = tid & 15;          // n-group 0..15
    const int ty = tid >> 4;          // m-group 0..15
    const int mbase = blockIdx.y * 128;
    const int nbase = blockIdx.x * 128;

    if (GATHER) {
        if (tid < 128) idx_s[tid] = idx[mbase + tid];
        __syncthreads();
    }

    unsigned long long acc[8][4];
#pragma unroll
    for (int i = 0; i < 8; i++)
#pragma unroll
        for (int j = 0; j < 4; j++) acc[i][j] = 0ull;

    for (int kc = 0; kc < K; kc += 32) {
        // load A tile -> As[k][m]
#pragma unroll
        for (int l = 0; l < 4; l++) {
            int f = tid + l * 256;            // 0..1023 (float4 units)
            int row = f >> 3;                 // 0..127
            int c4 = f & 7;                   // 0..7
            const float* ar = GATHER ? (A + (size_t)idx_s[row] * K)
                                     : (A + (size_t)(mbase + row) * K);
            float4 v = *(const float4*)(ar + kc + c4 * 4);
            As[c4 * 4 + 0][row] = v.x;
            As[c4 * 4 + 1][row] = v.y;
            As[c4 * 4 + 2][row] = v.z;
            As[c4 * 4 + 3][row] = v.w;
        }
        // load B tile -> Bs[k][n]
#pragma unroll
        for (int l = 0; l < 4; l++) {
            int f = tid + l * 256;
            int row = f >> 3;
            int c4 = f & 7;
            const float* br = B + (size_t)(nbase + row) * K;
            float4 v = *(const float4*)(br + kc + c4 * 4);
            Bs[c4 * 4 + 0][row] = v.x;
            Bs[c4 * 4 + 1][row] = v.y;
            Bs[c4 * 4 + 2][row] = v.z;
            Bs[c4 * 4 + 3][row] = v.w;
        }
        __syncthreads();

#pragma unroll
        for (int k = 0; k < 32; k++) {
            float4 a0 = *(const float4*)&As[k][ty * 8];
            float4 a1 = *(const float4*)&As[k][ty * 8 + 4];
            ulonglong2 bA = *(const ulonglong2*)&Bs[k][tx * 8];
            ulonglong2 bB = *(const ulonglong2*)&Bs[k][tx * 8 + 4];
            float av[8] = {a0.x, a0.y, a0.z, a0.w, a1.x, a1.y, a1.z, a1.w};
#pragma unroll
            for (int i = 0; i < 8; i++) {
                unsigned long long ad = dup_f32(av[i]);
                fma_f32x2(acc[i][0], ad, bA.x);
                fma_f32x2(acc[i][1], ad, bA.y);
                fma_f32x2(acc[i][2], ad, bB.x);
                fma_f32x2(acc[i][3], ad, bB.y);
            }
        }
        __syncthreads();
    }

    if (EPI == 0) {
#pragma unroll
        for (int i = 0; i < 8; i++) {
            int m = mbase + ty * 8 + i;
            float* cr = C + (size_t)m * N + nbase + tx * 8;
#pragma unroll
            for (int j = 0; j < 4; j++) {
                float2 v = unpack2(acc[i][j]);
                int n = nbase + tx * 8 + j * 2;
                float b0 = bias1[n], b1 = bias1[n + 1];
                if (bias2) { b0 += bias2[n]; b1 += bias2[n + 1]; }
                cr[j * 2 + 0] = v.x + b0;
                cr[j * 2 + 1] = v.y + b1;
            }
        }
    } else {
#pragma unroll
        for (int i = 0; i < 8; i++) {
            float vals[8];
#pragma unroll
            for (int j = 0; j < 4; j++) {
                float2 v = unpack2(acc[i][j]);
                int n = nbase + tx * 8 + j * 2;
                vals[j * 2 + 0] = v.x + bias1[n];
                vals[j * 2 + 1] = v.y + bias1[n + 1];
            }
            float mloc = vals[0];
#pragma unroll
            for (int j = 1; j < 8; j++) mloc = fmaxf(mloc, vals[j]);
#pragma unroll
            for (int o = 8; o; o >>= 1)
                mloc = fmaxf(mloc, __shfl_xor_sync(0xffffffffu, mloc, o));
            float sloc = 0.f;
#pragma unroll
            for (int j = 0; j < 8; j++) sloc += __expf(vals[j] - mloc);
#pragma unroll
            for (int o = 8; o; o >>= 1)
                sloc += __shfl_xor_sync(0xffffffffu, sloc, o);
            if (tx == 0) {
                int m = mbase + ty * 8 + i;
                redm[(size_t)m * nvt + blockIdx.x] = mloc;
                reds[(size_t)m * nvt + blockIdx.x] = sloc;
            }
        }
    }
}

// ---------------------------------------------------------------------------
// Persistent LSTM kernel: 128 blocks x 256 threads. Block b owns 8 hidden
// channels (ch0 = 8b) => 32 rows of Whh, held ENTIRELY IN REGISTERS:
// thread (warp w, lane l) owns rows r0=4w..4w+3, cols {l*4 + 128i + j}.
// 128 weight floats/thread (64 x f32x2). Per step: 8 LDS.128 of h + 64 FFMA2.
// Barrier (R8, proven): single counter, tid0-only release-RED arrival +
// tid0-only tight acquire poll. No per-producer MEMBAR.
// ---------------------------------------------------------------------------
__global__ void __launch_bounds__(256, 1)
lstm_kernel(const float* __restrict__ Whh, const float* __restrict__ X,
            const float* __restrict__ cinit, float* __restrict__ cout_,
            float* __restrict__ hs_out, int steps) {
    __shared__ __align__(16) float hs_s[HV];
    __shared__ float gates_s[32];

    const int tid = threadIdx.x;
    const int ch0 = blockIdx.x * 8;
    const int warp = tid >> 5;
    const int lane = tid & 31;
    const int r0 = warp * 4;          // 4 rows per warp

    // ---- load this thread's weight tile into registers ----
    // w[r][i] holds cols (lane*4 + i*128 .. +3) of global row
    // gate*HV + ch0 + lc, where rr = r0 + r, gate = rr>>3, lc = rr&7.
    ulonglong2 w[4][8];
#pragma unroll
    for (int r = 0; r < 4; r++) {
        int rr = r0 + r;
        int gate = rr >> 3, lc = rr & 7;
        const float* gw = Whh + (size_t)(gate * HV + ch0 + lc) * HV;
#pragma unroll
        for (int i = 0; i < 8; i++) {
            w[r][i] = *(const ulonglong2*)(gw + lane * 4 + i * 128);
        }
    }

    float c_val = 0.f;
    if (tid < 8) c_val = cinit ? cinit[ch0 + tid] : 0.f;
    __syncthreads();

    unsigned* barp = &g_bar;

    for (int t = 0; t < steps; t++) {
        // Prefetch this step's X gate pre-activations (independent of h).
        float xi, xf, xg, xo;
        if (tid < 8) {
            const float* Xr = X + (size_t)t * G4 + ch0 + tid;
            xi = Xr[0 * HV];
            xf = Xr[1 * HV];
            xg = Xr[2 * HV];
            xo = Xr[3 * HV];
        }

        // load h(t) from global (L2-coherent path; L1 may be stale)
        float4 hv = __ldcg(((const float4*)(g_hbuf + (t & 1) * HV)) + tid);
        *(float4*)&hs_s[tid * 4] = hv;
        __syncthreads();

        // GEMV: weights from registers, h from SMEM (conflict-free pattern)
        unsigned long long acc[4][2];
#pragma unroll
        for (int r = 0; r < 4; r++) { acc[r][0] = 0ull; acc[r][1] = 0ull; }
#pragma unroll
        for (int i = 0; i < 8; i++) {
            ulonglong2 h2 = *(const ulonglong2*)&hs_s[lane * 4 + i * 128];
#pragma unroll
            for (int r = 0; r < 4; r++) {
                fma_f32x2(acc[r][0], w[r][i].x, h2.x);
                fma_f32x2(acc[r][1], w[r][i].y, h2.y);
            }
        }
        float v[4];
#pragma unroll
        for (int r = 0; r < 4; r++) {
            float2 a = unpack2(acc[r][0]);
            float2 b = unpack2(acc[r][1]);
            v[r] = (a.x + a.y) + (b.x + b.y);
        }
#pragma unroll
        for (int o = 16; o; o >>= 1) {
            v[0] += __shfl_xor_sync(0xffffffffu, v[0], o);
            v[1] += __shfl_xor_sync(0xffffffffu, v[1], o);
            v[2] += __shfl_xor_sync(0xffffffffu, v[2], o);
            v[3] += __shfl_xor_sync(0xffffffffu, v[3], o);
        }
        if (lane == 0) {
            gates_s[r0 + 0] = v[0];
            gates_s[r0 + 1] = v[1];
            gates_s[r0 + 2] = v[2];
            gates_s[r0 + 3] = v[3];
        }
        __syncthreads();

        if (tid < 8) {
            int lc = tid;
            float gi = gates_s[0 * 8 + lc] + xi;
            float gf = gates_s[1 * 8 + lc] + xf;
            float gg = gates_s[2 * 8 + lc] + xg;
            float go = gates_s[3 * 8 + lc] + xo;
            float iv = 1.f / (1.f + expf(-gi));
            float fv = 1.f / (1.f + expf(-gf));
            float gv = tanhf(gg);
            float ov = 1.f / (1.f + expf(-go));
            c_val = fv * c_val + iv * gv;
            float hval = ov * tanhf(c_val);
            g_hbuf[((t + 1) & 1) * HV + ch0 + lc] = hval;
            if (hs_out) hs_out[(size_t)t * HV + ch0 + lc] = hval;
            if (cout_ && t == steps - 1) cout_[ch0 + lc] = tanhf(hval);
        }
        // Intra-block HB edge: producers' h stores happen-before tid0's
        // release-arrival below; consumers chain through their acquire poll.
        __syncthreads();

        if (tid == 0) {
            asm volatile("red.release.gpu.global.add.u32 [%0], 1;"
                         :: "l"(barp) : "memory");
            unsigned tgt = (unsigned)(t + 1) * gridDim.x;
            unsigned vv;
            do {
                asm volatile("ld.acquire.gpu.global.u32 %0, [%1];"
                             : "=r"(vv) : "l"(barp) : "memory");
            } while (vv < tgt);
        }
        __syncthreads();
    }
}

// ---------------------------------------------------------------------------
// Finalize: one warp per target position t.
//   loss[t] = logsumexp_v(logits[t]) - logit[t, target[t]]
// ---------------------------------------------------------------------------
__global__ void finalize_kernel(const int* __restrict__ target,
                                const float* __restrict__ Wout,
                                const float* __restrict__ bout,
                                const float* __restrict__ hs,
                                const float* __restrict__ redm,
                                const float* __restrict__ reds,
                                float* __restrict__ out) {
    int gwarp = (blockIdx.x * blockDim.x + threadIdx.x) >> 5;
    int lane = threadIdx.x & 31;
    if (gwarp >= SV) return;
    int t = gwarp;

    float M = -INFINITY, S = 0.f;
    for (int c = lane; c < NVT; c += 32) {
        float m = redm[(size_t)t * NVT + c];
        float s = reds[(size_t)t * NVT + c];
        float nm = fmaxf(M, m);
        S = S * __expf(M - nm) + s * __expf(m - nm);
        M = nm;
    }
#pragma unroll
    for (int o = 16; o; o >>= 1) {
        float m2 = __shfl_xor_sync(0xffffffffu, M, o);
        float s2 = __shfl_xor_sync(0xffffffffu, S, o);
        float nm = fmaxf(M, m2);
        S = S * __expf(M - nm) + s2 * __expf(m2 - nm);
        M = nm;
    }

    int tg = target[t];
    float dot = 0.f;
    const float* hr = hs + (size_t)t * HV;
    const float* wr = Wout + (size_t)tg * HV;
#pragma unroll
    for (int k = lane * 4; k < HV; k += 128) {
        float4 h4 = *(const float4*)(hr + k);
        float4 w4 = *(const float4*)(wr + k);
        dot += h4.x * w4.x + h4.y * w4.y + h4.z * w4.z + h4.w * w4.w;
    }
#pragma unroll
    for (int o = 16; o; o >>= 1) dot += __shfl_xor_sync(0xffffffffu, dot, o);

    if (lane == 0) out[t] = (M + logf(S)) - (dot + bout[tg]);
}

// ---------------------------------------------------------------------------
extern "C" void kernel_launch(void* const* d_in, const int* in_sizes, int n_in,
                              void* d_out, int out_size) {
    (void)in_sizes; (void)n_in; (void)out_size;
    const int*   src  = (const int*)d_in[0];
    const int*   tgt  = (const int*)d_in[1];
    const float* eEmb = (const float*)d_in[2];
    const float* eWih = (const float*)d_in[3];
    const float* eWhh = (const float*)d_in[4];
    const float* eBih = (const float*)d_in[5];
    const float* eBhh = (const float*)d_in[6];
    const float* dEmb = (const float*)d_in[7];
    const float* dWih = (const float*)d_in[8];
    const float* dWhh = (const float*)d_in[9];
    const float* dBih = (const float*)d_in[10];
    const float* dBhh = (const float*)d_in[11];
    const float* Wout = (const float*)d_in[12];
    const float* bout = (const float*)d_in[13];
    float* out = (float*)d_out;

    float *Xe, *Xd, *hbuf, *c0, *hs, *redm, *reds;
    unsigned* bar;
    cudaGetSymbolAddress((void**)&Xe, g_Xe);
    cudaGetSymbolAddress((void**)&Xd, g_Xd);
    cudaGetSymbolAddress((void**)&hbuf, g_hbuf);
    cudaGetSymbolAddress((void**)&c0, g_c0);
    cudaGetSymbolAddress((void**)&hs, g_hs);
    cudaGetSymbolAddress((void**)&redm, g_redm);
    cudaGetSymbolAddress((void**)&reds, g_reds);
    cudaGetSymbolAddress((void**)&bar, g_bar);

    cudaMemsetAsync(hbuf, 0, 2 * HV * sizeof(float));
    cudaMemsetAsync(bar, 0, sizeof(unsigned));

    // Precompute X = embed(tok) @ Wih^T + bih + bhh for both phases
    dim3 gX(G4 / 128, SV / 128);   // 32 x 4
    gemm_kernel<true, 0><<<gX, 256>>>(eEmb, src, eWih, eBih, eBhh,
                                      Xe, nullptr, nullptr, G4, EV, 0);
    gemm_kernel<true, 0><<<gX, 256>>>(dEmb, tgt, dWih, dBih, dBhh,
                                      Xd, nullptr, nullptr, G4, EV, 0);

    // Encoder recurrence (h0=c0=0). Final h lands in hbuf[0]; c0 = tanh(h).
    lstm_kernel<<<128, 256>>>(eWhh, Xe, nullptr, c0, nullptr, SV);
    cudaMemsetAsync(bar, 0, sizeof(unsigned));
    // Decoder recurrence, teacher-forced; stores all h_t.
    lstm_kernel<<<128, 256>>>(dWhh, Xd, c0, nullptr, hs, SV);

    // Output logits GEMM + per-tile streaming logsumexp stats
    dim3 gO(NVT, SV / 128);        // 250 x 4
    gemm_kernel<false, 1><<<gO, 256>>>(hs, nullptr, Wout, bout, nullptr,
                                       nullptr, redm, reds, VV, HV, NVT);

    // Combine tile stats + target logit -> losses
    finalize_kernel<<<(SV * 32 + 255) / 256, 256>>>(tgt, Wout, bout, hs,
                                                    redm, reds, out);
}